// round 2
// baseline (speedup 1.0000x reference)
#include <cuda_runtime.h>

#define Bb  4
#define Ss  512
#define NHh 12
#define DHh 64
#define HID 768
#define ROWS (Bb*Ss)   // 2048

// scratch (allocation-free rule: __device__ globals)
__device__ float g_q [ROWS*HID];          // [B,S,HID]
__device__ float g_kt[ROWS*HID];          // [B,NH,DH,S]  (transposed K)
__device__ float g_v [ROWS*HID];          // [B,S,HID]

// ---------------- QKV projection GEMM (at fp32 FMA roofline; unchanged) ----
#define BM 64
#define BN 64
#define BK 16

__global__ void __launch_bounds__(256) qkv_gemm(
    const float* __restrict__ A,
    const float* __restrict__ Wq, const float* __restrict__ bq,
    const float* __restrict__ Wk, const float* __restrict__ bk,
    const float* __restrict__ Wv, const float* __restrict__ bv)
{
    const int z = blockIdx.z;
    const float* W    = (z == 0) ? Wq : (z == 1) ? Wk : Wv;
    const float* bias = (z == 0) ? bq : (z == 1) ? bk : bv;

    __shared__ float As[BK][BM + 4];
    __shared__ float Ws[BK][BN];

    const int tid = threadIdx.x;
    const int rowBase = blockIdx.y * BM;
    const int colBase = blockIdx.x * BN;

    const int tm = (tid / 16) * 4;
    const int tn = (tid % 16) * 4;

    const int lm  = tid / 4;
    const int lk4 = (tid % 4) * 4;
    const int lwk = tid / 16;
    const int lwn = (tid % 16) * 4;

    float acc[4][4] = {};

    for (int k0 = 0; k0 < HID; k0 += BK) {
        __syncthreads();
        float4 av = *(const float4*)&A[(rowBase + lm) * HID + k0 + lk4];
        As[lk4 + 0][lm] = av.x;
        As[lk4 + 1][lm] = av.y;
        As[lk4 + 2][lm] = av.z;
        As[lk4 + 3][lm] = av.w;
        *(float4*)&Ws[lwk][lwn] =
            *(const float4*)&W[(k0 + lwk) * HID + colBase + lwn];
        __syncthreads();

        #pragma unroll
        for (int k = 0; k < BK; k++) {
            float4 a = *(const float4*)&As[k][tm];
            float4 w = *(const float4*)&Ws[k][tn];
            acc[0][0] += a.x * w.x; acc[0][1] += a.x * w.y; acc[0][2] += a.x * w.z; acc[0][3] += a.x * w.w;
            acc[1][0] += a.y * w.x; acc[1][1] += a.y * w.y; acc[1][2] += a.y * w.z; acc[1][3] += a.y * w.w;
            acc[2][0] += a.z * w.x; acc[2][1] += a.z * w.y; acc[2][2] += a.z * w.z; acc[2][3] += a.z * w.w;
            acc[3][0] += a.w * w.x; acc[3][1] += a.w * w.y; acc[3][2] += a.w * w.z; acc[3][3] += a.w * w.w;
        }
    }

    #pragma unroll
    for (int i = 0; i < 4; i++) {
        const int row = rowBase + tm + i;
        #pragma unroll
        for (int j = 0; j < 4; j++) {
            const int col = colBase + tn + j;
            const float c = acc[i][j] + bias[col];
            if (z == 0) {
                g_q[row * HID + col] = c;
            } else if (z == 2) {
                g_v[row * HID + col] = c;
            } else {
                const int b = row >> 9, s = row & 511;
                const int h = col >> 6, d = col & 63;
                g_kt[((b * NHh + h) * DHh + d) * Ss + s] = c;
            }
        }
    }
}

// ---------------- fused relational attention, v2 ----------------
// CTA = 2 q-rows of one batch, all 12 heads. 384 threads = 12 warps.
// warp role: pair p = wid%6 (heads 2p,2p+1), half g = wid/6.
//   score phase : g = k-half   (lane = one k of 64-block)
//   ctx   phase : g = d-half   (lane = one d of 64)
// rel read once from HBM; K/V amortized over 2 q-rows; ctx in registers.
#define TK 64

__global__ void __launch_bounds__(384) attn(
    const float* __restrict__ mask,   // [B,1,1,S]
    const float* __restrict__ rel,    // [B,S,S,DH]
    float* __restrict__ out)          // [B,S,HID]
{
    const int cta  = blockIdx.x;          // 1024 CTAs
    const int b    = cta >> 8;
    const int q0   = (cta & 255) << 1;    // q0, q0+1
    const int tid  = threadIdx.x;
    const int wid  = tid >> 5;
    const int lane = tid & 31;

    __shared__ float rel_s[2][TK][DHh + 1];   // [qi][k][d], pad 65
    __shared__ float q_s[HID * 2];            // [(h*64+d)*2 + qi], pre-scaled
    __shared__ float sc[NHh][TK][2];          // [h][k][qi]  scores -> probs
    __shared__ float m_s[2][NHh], l_s[2][NHh], alpha_s[2][NHh];

    for (int i = tid; i < HID; i += 384) {
        q_s[i * 2 + 0] = g_q[(b * Ss + q0)     * HID + i] * 0.125f;
        q_s[i * 2 + 1] = g_q[(b * Ss + q0 + 1) * HID + i] * 0.125f;
    }
    if (tid < 24) {
        m_s[tid / 12][tid % 12] = -1e30f;
        l_s[tid / 12][tid % 12] = 0.f;
    }

    const int pw = wid % 6;           // head pair
    const int gw = wid / 6;           // half selector
    const int h0 = pw * 2, h1 = h0 + 1;

    float ctx[2][2] = {};             // [hi][qi], persists across k-blocks

    for (int kb = 0; kb < Ss; kb += TK) {
        __syncthreads();
        // ---- stage rel blocks for both q rows (transposed? no: [k][d] row-major)
        for (int i = tid; i < 2 * TK * 16; i += 384) {
            const int qi = i >> 10;               // TK*16 = 1024
            const int r  = i & 1023;
            const int k  = r >> 4;
            const int d4 = (r & 15) << 2;
            float4 v = *(const float4*)&rel[
                (((long)(b * Ss + q0 + qi) * Ss) + kb + k) * DHh + d4];
            rel_s[qi][k][d4 + 0] = v.x;
            rel_s[qi][k][d4 + 1] = v.y;
            rel_s[qi][k][d4 + 2] = v.z;
            rel_s[qi][k][d4 + 3] = v.w;
        }
        __syncthreads();

        // ---- scores: warp (pair, k-half); lane = k. q.(K + rel) folded.
        {
            const int k = (gw << 5) + lane;
            const float* kt0 = g_kt + ((b * NHh + h0) * DHh) * Ss + kb + k;
            const float* kt1 = kt0 + DHh * Ss;
            float a00 = 0.f, a01 = 0.f, a10 = 0.f, a11 = 0.f;
            #pragma unroll 4
            for (int d = 0; d < DHh; d++) {
                const float r0 = rel_s[0][k][d];
                const float r1 = rel_s[1][k][d];
                const float kv0 = kt0[d * Ss];
                const float kv1 = kt1[d * Ss];
                const float2 qa = *(const float2*)&q_s[(h0 * DHh + d) * 2];
                const float2 qb = *(const float2*)&q_s[(h1 * DHh + d) * 2];
                a00 += qa.x * (kv0 + r0);
                a01 += qa.y * (kv0 + r1);
                a10 += qb.x * (kv1 + r0);
                a11 += qb.y * (kv1 + r1);
            }
            const float mv = mask[b * Ss + kb + k];
            sc[h0][k][0] = a00 + mv;
            sc[h0][k][1] = a01 + mv;
            sc[h1][k][0] = a10 + mv;
            sc[h1][k][1] = a11 + mv;
        }
        __syncthreads();

        // ---- online softmax: 24 units (h, qi) over 12 warps
        for (int u = wid; u < 24; u += 12) {
            const int h = u % 12, qi = u / 12;
            float x0 = sc[h][lane][qi];
            float x1 = sc[h][lane + 32][qi];
            float mx = fmaxf(x0, x1);
            #pragma unroll
            for (int o = 16; o; o >>= 1) mx = fmaxf(mx, __shfl_xor_sync(0xffffffffu, mx, o));
            const float mnew = fmaxf(m_s[qi][h], mx);
            const float p0 = __expf(x0 - mnew);
            const float p1 = __expf(x1 - mnew);
            sc[h][lane][qi]      = p0;
            sc[h][lane + 32][qi] = p1;
            float ls = p0 + p1;
            #pragma unroll
            for (int o = 16; o; o >>= 1) ls += __shfl_xor_sync(0xffffffffu, ls, o);
            if (lane == 0) {
                const float alpha = __expf(m_s[qi][h] - mnew);
                alpha_s[qi][h] = alpha;
                l_s[qi][h]     = l_s[qi][h] * alpha + ls;
                m_s[qi][h]     = mnew;
            }
        }
        __syncthreads();

        // ---- ctx accumulate: warp (pair, d-half); lane = d. registers only.
        {
            const int d = (gw << 5) + lane;
            ctx[0][0] *= alpha_s[0][h0];
            ctx[0][1] *= alpha_s[1][h0];
            ctx[1][0] *= alpha_s[0][h1];
            ctx[1][1] *= alpha_s[1][h1];
            const float* vp = g_v + (long)(b * Ss + kb) * HID + d;
            #pragma unroll 4
            for (int k = 0; k < TK; k++) {
                const float r0 = rel_s[0][k][d];
                const float r1 = rel_s[1][k][d];
                const float2 p0 = *(const float2*)&sc[h0][k][0];
                const float2 p1 = *(const float2*)&sc[h1][k][0];
                const float v0 = vp[k * HID + h0 * DHh];
                const float v1 = vp[k * HID + h1 * DHh];
                ctx[0][0] += p0.x * (v0 + r0);
                ctx[0][1] += p0.y * (v0 + r1);
                ctx[1][0] += p1.x * (v1 + r0);
                ctx[1][1] += p1.y * (v1 + r1);
            }
        }
    }

    // ---- write out: each (h,d,qi) owned by exactly one thread
    {
        const int d = (gw << 5) + lane;
        out[(long)(b * Ss + q0)     * HID + h0 * DHh + d] = ctx[0][0] / l_s[0][h0];
        out[(long)(b * Ss + q0 + 1) * HID + h0 * DHh + d] = ctx[0][1] / l_s[1][h0];
        out[(long)(b * Ss + q0)     * HID + h1 * DHh + d] = ctx[1][0] / l_s[0][h1];
        out[(long)(b * Ss + q0 + 1) * HID + h1 * DHh + d] = ctx[1][1] / l_s[1][h1];
    }
}

extern "C" void kernel_launch(void* const* d_in, const int* in_sizes, int n_in,
                              void* d_out, int out_size)
{
    const float* hidden = (const float*)d_in[0];
    const float* mask   = (const float*)d_in[1];
    const float* rel    = (const float*)d_in[2];
    const float* Wq     = (const float*)d_in[3];
    const float* bq     = (const float*)d_in[4];
    const float* Wk     = (const float*)d_in[5];
    const float* bk     = (const float*)d_in[6];
    const float* Wv     = (const float*)d_in[7];
    const float* bv     = (const float*)d_in[8];
    float* out = (float*)d_out;

    dim3 g(HID / BN, ROWS / BM, 3);
    qkv_gemm<<<g, 256>>>(hidden, Wq, bq, Wk, bk, Wv, bv);
    attn<<<ROWS / 2, 384>>>(mask, rel, out);
}

// round 3
// speedup vs baseline: 1.2252x; 1.2252x over previous
#include <cuda_runtime.h>

#define Bb  4
#define Ss  512
#define NHh 12
#define DHh 64
#define HID 768
#define ROWS (Bb*Ss)   // 2048

// scratch (allocation-free rule: __device__ globals)
__device__ float g_q [ROWS*HID];          // [B,S,HID]
__device__ float g_kt[ROWS*HID];          // [B,NH,DH,S]  (transposed K)
__device__ float g_v [ROWS*HID];          // [B,S,HID]

// ---------------- QKV projection GEMM (at fp32 FMA roofline; unchanged) ----
#define BM 64
#define BN 64
#define BK 16

__global__ void __launch_bounds__(256) qkv_gemm(
    const float* __restrict__ A,
    const float* __restrict__ Wq, const float* __restrict__ bq,
    const float* __restrict__ Wk, const float* __restrict__ bk,
    const float* __restrict__ Wv, const float* __restrict__ bv)
{
    const int z = blockIdx.z;
    const float* W    = (z == 0) ? Wq : (z == 1) ? Wk : Wv;
    const float* bias = (z == 0) ? bq : (z == 1) ? bk : bv;

    __shared__ float As[BK][BM + 4];
    __shared__ float Ws[BK][BN];

    const int tid = threadIdx.x;
    const int rowBase = blockIdx.y * BM;
    const int colBase = blockIdx.x * BN;

    const int tm = (tid / 16) * 4;
    const int tn = (tid % 16) * 4;

    const int lm  = tid / 4;
    const int lk4 = (tid % 4) * 4;
    const int lwk = tid / 16;
    const int lwn = (tid % 16) * 4;

    float acc[4][4] = {};

    for (int k0 = 0; k0 < HID; k0 += BK) {
        __syncthreads();
        float4 av = *(const float4*)&A[(rowBase + lm) * HID + k0 + lk4];
        As[lk4 + 0][lm] = av.x;
        As[lk4 + 1][lm] = av.y;
        As[lk4 + 2][lm] = av.z;
        As[lk4 + 3][lm] = av.w;
        *(float4*)&Ws[lwk][lwn] =
            *(const float4*)&W[(k0 + lwk) * HID + colBase + lwn];
        __syncthreads();

        #pragma unroll
        for (int k = 0; k < BK; k++) {
            float4 a = *(const float4*)&As[k][tm];
            float4 w = *(const float4*)&Ws[k][tn];
            acc[0][0] += a.x * w.x; acc[0][1] += a.x * w.y; acc[0][2] += a.x * w.z; acc[0][3] += a.x * w.w;
            acc[1][0] += a.y * w.x; acc[1][1] += a.y * w.y; acc[1][2] += a.y * w.z; acc[1][3] += a.y * w.w;
            acc[2][0] += a.z * w.x; acc[2][1] += a.z * w.y; acc[2][2] += a.z * w.z; acc[2][3] += a.z * w.w;
            acc[3][0] += a.w * w.x; acc[3][1] += a.w * w.y; acc[3][2] += a.w * w.z; acc[3][3] += a.w * w.w;
        }
    }

    #pragma unroll
    for (int i = 0; i < 4; i++) {
        const int row = rowBase + tm + i;
        #pragma unroll
        for (int j = 0; j < 4; j++) {
            const int col = colBase + tn + j;
            const float c = acc[i][j] + bias[col];
            if (z == 0) {
                g_q[row * HID + col] = c;
            } else if (z == 2) {
                g_v[row * HID + col] = c;
            } else {
                const int b = row >> 9, s = row & 511;
                const int h = col >> 6, d = col & 63;
                g_kt[((b * NHh + h) * DHh + d) * Ss + s] = c;
            }
        }
    }
}

// ---------------- fused relational attention, v3 ----------------
// CTA = 4 q-rows, all 12 heads. 384 threads = 12 warps.
// warp role: pair p = wid%6 (heads 2p,2p+1), half g = wid/6.
//   score phase : lane = k in half-block
//   ctx   phase : lane = d in half-dim
// Dynamic SMEM (~92 KB): rel read once from HBM; K/V amortized over
// 4 q-rows; batched LDGs (MLP=8); ctx accumulators in registers.
#define TQ 4
#define TK 64
#define RELW (DHh + 1)

#define Q_OFF   (TQ * TK * RELW)              // 16640
#define SC_OFF  (Q_OFF + HID * TQ)            // +3072
#define ML_OFF  (SC_OFF + NHh * TK * TQ)      // +3072
#define SM_FLOATS (ML_OFF + 3 * TQ * NHh)     // +144
#define SM_BYTES  (SM_FLOATS * 4)             // 91,712

__global__ void __launch_bounds__(384) attn(
    const float* __restrict__ mask,   // [B,1,1,S]
    const float* __restrict__ rel,    // [B,S,S,DH]
    float* __restrict__ out)          // [B,S,HID]
{
    extern __shared__ float sm[];
    float* rel_s = sm;                  // [qi][k][d]: (qi*TK+k)*RELW + d
    float* q_s   = sm + Q_OFF;          // [h*64+d][qi], pre-scaled
    float* sc    = sm + SC_OFF;         // [h][k][qi]
    float* m_s   = sm + ML_OFF;         // [qi*12+h]
    float* l_s   = m_s + TQ * NHh;
    float* al_s  = l_s + TQ * NHh;

    const int cta  = blockIdx.x;          // 512
    const int b    = cta >> 7;            // 128 CTAs / batch
    const int q0   = (cta & 127) << 2;
    const int tid  = threadIdx.x;
    const int wid  = tid >> 5;
    const int lane = tid & 31;

    for (int i = tid; i < HID; i += 384) {
        #pragma unroll
        for (int qi = 0; qi < TQ; qi++)
            q_s[i * TQ + qi] = g_q[(b * Ss + q0 + qi) * HID + i] * 0.125f;
    }
    if (tid < TQ * NHh) { m_s[tid] = -1e30f; l_s[tid] = 0.f; }

    const int pw = wid % 6;
    const int gw = wid / 6;
    const int h0 = pw * 2, h1 = h0 + 1;

    float ctx0[TQ] = {}, ctx1[TQ] = {};   // persist across k-blocks

    for (int kb = 0; kb < Ss; kb += TK) {
        __syncthreads();
        // ---- stage rel [TQ][TK][64] (coalesced float4)
        for (int i = tid; i < TQ * TK * 16; i += 384) {
            const int qi = i >> 10;          // TK*16 = 1024
            const int r  = i & 1023;
            const int k  = r >> 4;
            const int d4 = (r & 15) << 2;
            float4 v = *(const float4*)&rel[
                (((long)(b * Ss + q0 + qi)) * Ss + kb + k) * DHh + d4];
            float* dst = &rel_s[(qi * TK + k) * RELW + d4];
            dst[0] = v.x; dst[1] = v.y; dst[2] = v.z; dst[3] = v.w;
        }
        __syncthreads();

        // ---- scores: lane = k, 4 q-rows, 2 heads; batched K loads (MLP 8)
        {
            const int k = (gw << 5) + lane;
            const float* kt0 = g_kt + ((b * NHh + h0) * DHh) * Ss + kb + k;
            const float* kt1 = kt0 + DHh * Ss;
            const float* rl  = &rel_s[k * RELW];
            float a0[TQ] = {}, a1[TQ] = {};
            #pragma unroll
            for (int d0 = 0; d0 < DHh; d0 += 4) {
                float kv0[4], kv1[4];
                #pragma unroll
                for (int j = 0; j < 4; j++) {
                    kv0[j] = kt0[(d0 + j) * Ss];
                    kv1[j] = kt1[(d0 + j) * Ss];
                }
                #pragma unroll
                for (int j = 0; j < 4; j++) {
                    const int d = d0 + j;
                    float4 qa4 = *(const float4*)&q_s[(h0 * DHh + d) * TQ];
                    float4 qb4 = *(const float4*)&q_s[(h1 * DHh + d) * TQ];
                    const float qa[4] = {qa4.x, qa4.y, qa4.z, qa4.w};
                    const float qb[4] = {qb4.x, qb4.y, qb4.z, qb4.w};
                    float rr[TQ];
                    #pragma unroll
                    for (int qi = 0; qi < TQ; qi++)
                        rr[qi] = rl[qi * TK * RELW + d];
                    #pragma unroll
                    for (int qi = 0; qi < TQ; qi++) {
                        a0[qi] += qa[qi] * kv0[j];
                        a0[qi] += qa[qi] * rr[qi];
                        a1[qi] += qb[qi] * kv1[j];
                        a1[qi] += qb[qi] * rr[qi];
                    }
                }
            }
            const float mv = mask[b * Ss + kb + k];
            float4 s0 = {a0[0] + mv, a0[1] + mv, a0[2] + mv, a0[3] + mv};
            float4 s1 = {a1[0] + mv, a1[1] + mv, a1[2] + mv, a1[3] + mv};
            *(float4*)&sc[(h0 * TK + k) * TQ] = s0;
            *(float4*)&sc[(h1 * TK + k) * TQ] = s1;
        }
        __syncthreads();

        // ---- online softmax: 48 units (h,qi), 4 per warp
        #pragma unroll
        for (int j = 0; j < 4; j++) {
            const int u  = wid + 12 * j;
            const int h  = u % 12, qi = u / 12;
            float x0 = sc[(h * TK + lane) * TQ + qi];
            float x1 = sc[(h * TK + lane + 32) * TQ + qi];
            float mx = fmaxf(x0, x1);
            #pragma unroll
            for (int o = 16; o; o >>= 1) mx = fmaxf(mx, __shfl_xor_sync(0xffffffffu, mx, o));
            const float mnew = fmaxf(m_s[qi * NHh + h], mx);
            const float p0 = __expf(x0 - mnew);
            const float p1 = __expf(x1 - mnew);
            sc[(h * TK + lane) * TQ + qi]      = p0;
            sc[(h * TK + lane + 32) * TQ + qi] = p1;
            float ls = p0 + p1;
            #pragma unroll
            for (int o = 16; o; o >>= 1) ls += __shfl_xor_sync(0xffffffffu, ls, o);
            if (lane == 0) {
                const float alpha = __expf(m_s[qi * NHh + h] - mnew);
                al_s[qi * NHh + h] = alpha;
                l_s[qi * NHh + h]  = l_s[qi * NHh + h] * alpha + ls;
                m_s[qi * NHh + h]  = mnew;
            }
        }
        __syncthreads();

        // ---- ctx: lane = d, 4 q-rows, 2 heads; batched V loads (MLP 8)
        {
            const int d = (gw << 5) + lane;
            #pragma unroll
            for (int qi = 0; qi < TQ; qi++) {
                ctx0[qi] *= al_s[qi * NHh + h0];
                ctx1[qi] *= al_s[qi * NHh + h1];
            }
            const float* vp = g_v + (long)(b * Ss + kb) * HID + d;
            const float* rl = &rel_s[0];
            #pragma unroll
            for (int k0 = 0; k0 < TK; k0 += 4) {
                float v0[4], v1[4];
                #pragma unroll
                for (int j = 0; j < 4; j++) {
                    v0[j] = vp[(k0 + j) * HID + h0 * DHh];
                    v1[j] = vp[(k0 + j) * HID + h1 * DHh];
                }
                #pragma unroll
                for (int j = 0; j < 4; j++) {
                    const int k = k0 + j;
                    float4 p04 = *(const float4*)&sc[(h0 * TK + k) * TQ];
                    float4 p14 = *(const float4*)&sc[(h1 * TK + k) * TQ];
                    const float p0[4] = {p04.x, p04.y, p04.z, p04.w};
                    const float p1[4] = {p14.x, p14.y, p14.z, p14.w};
                    float rr[TQ];
                    #pragma unroll
                    for (int qi = 0; qi < TQ; qi++)
                        rr[qi] = rl[(qi * TK + k) * RELW + d];
                    #pragma unroll
                    for (int qi = 0; qi < TQ; qi++) {
                        ctx0[qi] += p0[qi] * v0[j];
                        ctx0[qi] += p0[qi] * rr[qi];
                        ctx1[qi] += p1[qi] * v1[j];
                        ctx1[qi] += p1[qi] * rr[qi];
                    }
                }
            }
        }
    }

    // ---- write out
    {
        const int d = (gw << 5) + lane;
        #pragma unroll
        for (int qi = 0; qi < TQ; qi++) {
            out[(long)(b * Ss + q0 + qi) * HID + h0 * DHh + d] =
                ctx0[qi] / l_s[qi * NHh + h0];
            out[(long)(b * Ss + q0 + qi) * HID + h1 * DHh + d] =
                ctx1[qi] / l_s[qi * NHh + h1];
        }
    }
}

extern "C" void kernel_launch(void* const* d_in, const int* in_sizes, int n_in,
                              void* d_out, int out_size)
{
    const float* hidden = (const float*)d_in[0];
    const float* mask   = (const float*)d_in[1];
    const float* rel    = (const float*)d_in[2];
    const float* Wq     = (const float*)d_in[3];
    const float* bq     = (const float*)d_in[4];
    const float* Wk     = (const float*)d_in[5];
    const float* bk     = (const float*)d_in[6];
    const float* Wv     = (const float*)d_in[7];
    const float* bv     = (const float*)d_in[8];
    float* out = (float*)d_out;

    cudaFuncSetAttribute(attn, cudaFuncAttributeMaxDynamicSharedMemorySize, SM_BYTES);

    dim3 g(HID / BN, ROWS / BM, 3);
    qkv_gemm<<<g, 256>>>(hidden, Wq, bq, Wk, bk, Wv, bv);
    attn<<<ROWS / TQ, 384, SM_BYTES>>>(mask, rel, out);
}